// round 6
// baseline (speedup 1.0000x reference)
#include <cuda_runtime.h>
#include <cstdint>

typedef unsigned long long u64;
typedef unsigned int u32;

#define NB    64
#define CIN   256
#define HH    56
#define WW    56
#define HW    3136
#define NPIX  200704   // NB*HW
#define NQUAD 50176    // NPIX/4
#define NWRD  6272     // NPIX/32
#define CNTD  200704.0
#define EPSD  1e-5
#define PADW  58
#define PADHW 3364     // 58*58

// ---------------- static device scratch ----------------
__device__ u64  g_w1b[64 * 4];
__device__ u64  g_w2b[64 * 9];
__device__ u64  g_w3b[256];
__device__ int  g_ctab[9 * 64];       // border-pattern corrections for conv2
__device__ int4 g_s1v[8 * NPIX];      // conv1 outputs int16, [group][pixel]
__device__ short g_s2[NPIX * 64];     // conv2 outputs int16, [pixel][ch]
__device__ u64  g_a1p[NB * PADHW];    // conv2 input bits, zero halo
__device__ ulonglong4 g_a2[NQUAD];    // conv3 input bits (pixel-major u64)
__device__ u32  g_t3[NWRD * 64];      // transposed conv3 input bits: [pixword][bit]
__device__ int  g_G[4096];            // gram xor-popc, upper triangle i<j
__device__ int  g_n3[64];             // per-bit set counts
__device__ long long g_sum1[64], g_ss1[64];
__device__ long long g_sum2[64], g_ss2[64];
__device__ float g_A3[256], g_B3[256];

// ---------------- K0: zero scratch + pack weights + border table ----------------
__global__ void k0_init(const float* __restrict__ w1,
                        const float* __restrict__ w2,
                        const float* __restrict__ w3) {
    const int t = threadIdx.x;   // 576 threads
    if (t < 64) {
        u64 wd0 = 0, wd1 = 0, wd2 = 0, wd3 = 0;
        const float* wp = w1 + t * 256;
        #pragma unroll 8
        for (int c = 0; c < 64; c++) wd0 |= (u64)(wp[c]       > 0.f) << c;
        #pragma unroll 8
        for (int c = 0; c < 64; c++) wd1 |= (u64)(wp[c + 64]  > 0.f) << c;
        #pragma unroll 8
        for (int c = 0; c < 64; c++) wd2 |= (u64)(wp[c + 128] > 0.f) << c;
        #pragma unroll 8
        for (int c = 0; c < 64; c++) wd3 |= (u64)(wp[c + 192] > 0.f) << c;
        g_w1b[t * 4 + 0] = wd0; g_w1b[t * 4 + 1] = wd1;
        g_w1b[t * 4 + 2] = wd2; g_w1b[t * 4 + 3] = wd3;
        g_sum1[t] = 0; g_ss1[t] = 0; g_sum2[t] = 0; g_ss2[t] = 0;
        g_n3[t] = 0;
    }
    {   // w2 OIHW (64,64,3,3)
        const int co = t / 9, tap = t - co * 9;
        u64 wd = 0;
        #pragma unroll 8
        for (int ci = 0; ci < 64; ci++)
            wd |= (u64)(w2[(co * 64 + ci) * 9 + tap] > 0.f) << ci;
        g_w2b[t] = wd;
    }
    if (t < 256) {
        u64 wd = 0;
        #pragma unroll 8
        for (int ci = 0; ci < 64; ci++)
            wd |= (u64)(w3[t * 64 + ci] > 0.f) << ci;
        g_w3b[t] = wd;
    }
    for (int i = t; i < 4096; i += 576) g_G[i] = 0;
    __syncthreads();
    // Border correction table: what a zero halo word wrongly contributes.
    {
        const int pid = t / 64, co = t - pid * 64;  // pid<9
        const int rowc = pid / 3, colc = pid - rowc * 3;
        int corr = 0;
        #pragma unroll
        for (int tap = 0; tap < 9; tap++) {
            const int r = tap / 3, c = tap - r * 3;
            bool inval = (rowc == 1 && r == 0) || (rowc == 2 && r == 2) ||
                         (colc == 1 && c == 0) || (colc == 2 && c == 2);
            if (inval) corr += 64 - 2 * __popcll(g_w2b[co * 9 + tap]);
        }
        g_ctab[t] = corr;
    }
}

// ---------------- K1: pack x (4 px/thread, float4), conv1, stats ----------------
__global__ __launch_bounds__(128) void k1_conv1(const float* __restrict__ x) {
    __shared__ u64 w1s[256];
    __shared__ int ssum[64], sss[64];
    const int tid = threadIdx.x;
    if (tid < 64) { ssum[tid] = 0; sss[tid] = 0; }
    for (int i = tid; i < 256; i += 128) w1s[i] = g_w1b[i];
    __syncthreads();

    const int q  = blockIdx.x * 128 + tid;   // 392*128 = NQUAD
    const int n  = q / 784;
    const int hw = (q - n * 784) * 4;
    const float* xp = x + (size_t)n * CIN * HW + hw;

    u64 v[4][4];   // [pixel][word]
    #pragma unroll
    for (int wi = 0; wi < 4; wi++) {
        u64 b0 = 0, b1 = 0, b2 = 0, b3 = 0;
        #pragma unroll 8
        for (int c = 0; c < 64; c++) {
            float4 xv = *reinterpret_cast<const float4*>(xp + (size_t)(wi * 64 + c) * HW);
            b0 |= (u64)(xv.x > 0.f) << c;
            b1 |= (u64)(xv.y > 0.f) << c;
            b2 |= (u64)(xv.z > 0.f) << c;
            b3 |= (u64)(xv.w > 0.f) << c;
        }
        v[0][wi] = b0; v[1][wi] = b1; v[2][wi] = b2; v[3][wi] = b3;
    }

    const int lane = tid & 31;

    #pragma unroll 1
    for (int g = 0; g < 8; g++) {
        int pk[4][4];   // [pixel][jj]
        #pragma unroll
        for (int jj = 0; jj < 4; jj++) {
            int sv[4][2];
            #pragma unroll
            for (int k = 0; k < 2; k++) {
                const int co = g * 8 + jj * 2 + k;
                const u64* wq = &w1s[co * 4];
                const u64 q0 = wq[0], q1 = wq[1], q2 = wq[2], q3 = wq[3];
                int stot = 0, qtot = 0;
                #pragma unroll
                for (int j = 0; j < 4; j++) {
                    int d = __popcll(v[j][0] ^ q0) + __popcll(v[j][1] ^ q1)
                          + __popcll(v[j][2] ^ q2) + __popcll(v[j][3] ^ q3);
                    int s = 256 - 2 * d;
                    sv[j][k] = s; stot += s; qtot += s * s;
                }
                int rs = __reduce_add_sync(0xFFFFFFFFu, stot);
                int rq = __reduce_add_sync(0xFFFFFFFFu, qtot);
                if (lane == 0) { atomicAdd(&ssum[co], rs); atomicAdd(&sss[co], rq); }
            }
            #pragma unroll
            for (int j = 0; j < 4; j++)
                pk[j][jj] = (sv[j][0] & 0xFFFF) | (sv[j][1] << 16);
        }
        #pragma unroll
        for (int j = 0; j < 4; j++)
            g_s1v[(size_t)g * NPIX + 4 * q + j] = make_int4(pk[j][0], pk[j][1], pk[j][2], pk[j][3]);
    }
    __syncthreads();
    if (tid < 64) {
        atomicAdd((u64*)&g_sum1[tid], (u64)(long long)ssum[tid]);
        atomicAdd((u64*)&g_ss1[tid],  (u64)(long long)sss[tid]);
    }
}

// ---------------- K2: BN1 threshold -> padded conv2 input bits ----------------
__global__ __launch_bounds__(256) void k2_bnpack1(const float* __restrict__ g1,
                                                  const float* __restrict__ b1) {
    __shared__ float As[64], Bs[64];
    const int tid = threadIdx.x;
    if (tid < 64) {
        double m   = (double)g_sum1[tid] / CNTD;
        double var = (double)g_ss1[tid] / CNTD - m * m;
        double r   = rsqrt(var + EPSD);
        double A   = (double)g1[tid] * r;
        As[tid] = (float)A;
        Bs[tid] = (float)((double)b1[tid] - A * m);
    }
    __syncthreads();
    const int p = blockIdx.x * 256 + tid;
    u64 v = 0;
    #pragma unroll
    for (int g = 0; g < 8; g++) {
        int4 q = g_s1v[(size_t)g * NPIX + p];
        int arr[4] = {q.x, q.y, q.z, q.w};
        #pragma unroll
        for (int k = 0; k < 4; k++) {
            const int co = g * 8 + k * 2;
            float lo = (float)(short)arr[k];
            float hi = (float)(short)(arr[k] >> 16);
            v |= (u64)(fmaf(As[co],     lo, Bs[co])     > 0.f) << co;
            v |= (u64)(fmaf(As[co + 1], hi, Bs[co + 1]) > 0.f) << (co + 1);
        }
    }
    const int n  = p / HW;
    const int hw = p - n * HW;
    const int h  = hw / WW;
    const int w  = hw - h * WW;
    g_a1p[(size_t)n * PADHW + (size_t)(h + 1) * PADW + (w + 1)] = v;
}

// ---------------- K3: conv2 (3x3, pad 1) + stats ----------------
// Warp = (row, channel-half): 7168 jobs. Lane = channel (weights in regs).
// 4-pixel chunks: 12 batched loads, then 36 independent popc chains.
__global__ __launch_bounds__(256) void k3_conv2() {
    __shared__ int bsum[64], bsq[64];
    const int tid  = threadIdx.x;
    const int wid  = tid >> 5;
    const int lane = tid & 31;
    if (tid < 64) { bsum[tid] = 0; bsq[tid] = 0; }
    __syncthreads();

    const int job  = blockIdx.x * 8 + wid;   // 896 blocks * 8 = 7168 jobs
    const int half = job & 1;
    const int row  = job >> 1;               // 0..3583
    const int n    = row / HH;
    const int h    = row - n * HH;
    const int ch   = half * 32 + lane;

    u64 wv[9];
    #pragma unroll
    for (int t = 0; t < 9; t++) wv[t] = g_w2b[ch * 9 + t];

    const int rowc = (h == 0) ? 1 : ((h == HH - 1) ? 2 : 0);
    const int corr_m = g_ctab[(rowc * 3 + 0) * 64 + ch];
    const int corr_l = g_ctab[(rowc * 3 + 1) * 64 + ch];
    const int corr_r = g_ctab[(rowc * 3 + 2) * 64 + ch];

    const u64* r0 = g_a1p + (size_t)n * PADHW + (size_t)h * PADW;
    const u64* r1 = r0 + PADW;
    const u64* r2 = r1 + PADW;

    u64 a[3][6];
    a[0][0] = __ldg(r0 + 0); a[0][1] = __ldg(r0 + 1);
    a[1][0] = __ldg(r1 + 0); a[1][1] = __ldg(r1 + 1);
    a[2][0] = __ldg(r2 + 0); a[2][1] = __ldg(r2 + 1);

    short* orow = g_s2 + (size_t)(n * HW + h * WW) * 64 + ch;
    int accs = 0, accq = 0;

    #pragma unroll 1
    for (int c = 0; c < 14; c++) {
        const int base = c * 4;
        #pragma unroll
        for (int j = 0; j < 4; j++) {
            a[0][2 + j] = __ldg(r0 + base + 2 + j);
            a[1][2 + j] = __ldg(r1 + base + 2 + j);
            a[2][2 + j] = __ldg(r2 + base + 2 + j);
        }
        #pragma unroll
        for (int j = 0; j < 4; j++) {
            const int w = base + j;
            int d = __popcll(a[0][j] ^ wv[0]) + __popcll(a[0][j+1] ^ wv[1]) + __popcll(a[0][j+2] ^ wv[2])
                  + __popcll(a[1][j] ^ wv[3]) + __popcll(a[1][j+1] ^ wv[4]) + __popcll(a[1][j+2] ^ wv[5])
                  + __popcll(a[2][j] ^ wv[6]) + __popcll(a[2][j+1] ^ wv[7]) + __popcll(a[2][j+2] ^ wv[8]);
            const int corr = (w == 0) ? corr_l : ((w == WW - 1) ? corr_r : corr_m);
            int s = 576 - 2 * d - corr;
            accs += s; accq += s * s;
            orow[(size_t)w * 64] = (short)s;
        }
        #pragma unroll
        for (int r = 0; r < 3; r++) { a[r][0] = a[r][4]; a[r][1] = a[r][5]; }
    }

    atomicAdd(&bsum[ch], accs);
    atomicAdd(&bsq[ch],  accq);
    __syncthreads();
    if (tid < 64) {
        atomicAdd((u64*)&g_sum2[tid], (u64)(long long)bsum[tid]);
        atomicAdd((u64*)&g_ss2[tid],  (u64)(long long)bsq[tid]);
    }
}

// ---------------- K4: BN2 threshold -> conv3 bits + ballot transpose ----------------
__global__ __launch_bounds__(256) void k4_pack2(const float* __restrict__ g2,
                                                const float* __restrict__ b2) {
    __shared__ float As[64], Bs[64];
    const int tid = threadIdx.x;
    if (tid < 64) {
        double m   = (double)g_sum2[tid] / CNTD;
        double var = (double)g_ss2[tid] / CNTD - m * m;
        double r   = rsqrt(var + EPSD);
        double A   = (double)g2[tid] * r;
        As[tid] = (float)A;
        Bs[tid] = (float)((double)b2[tid] - A * m);
    }
    __syncthreads();

    const int p = blockIdx.x * 256 + tid;   // 784 blocks
    const int4* sp = reinterpret_cast<const int4*>(g_s2 + (size_t)p * 64);
    u64 v = 0;
    #pragma unroll
    for (int g = 0; g < 8; g++) {
        int4 qq = sp[g];
        int arr[4] = {qq.x, qq.y, qq.z, qq.w};
        #pragma unroll
        for (int k = 0; k < 4; k++) {
            const int co = g * 8 + k * 2;
            float lo = (float)(short)arr[k];
            float hi = (float)(short)(arr[k] >> 16);
            v |= (u64)(fmaf(As[co],     lo, Bs[co])     > 0.f) << co;
            v |= (u64)(fmaf(As[co + 1], hi, Bs[co + 1]) > 0.f) << (co + 1);
        }
    }
    reinterpret_cast<u64*>(g_a2)[p] = v;

    // ballot transpose: warp's 32 pixels x 64 bits -> 64 u32 column words
    const int lane = tid & 31;
    const int gw   = p >> 5;
    u32 r0 = 0, r1 = 0;
    #pragma unroll
    for (int b = 0; b < 64; b++) {
        u32 bl = __ballot_sync(0xFFFFFFFFu, (u32)((v >> b) & 1ull));
        if (b == lane)      r0 = bl;
        if (b == lane + 32) r1 = bl;
    }
    g_t3[(size_t)gw * 64 + lane]      = r0;
    g_t3[(size_t)gw * 64 + 32 + lane] = r1;
}

// ---------------- K4g: gram matrix of conv3 input bit-columns ----------------
__global__ __launch_bounds__(256) void k4g_gram() {
    __shared__ u32 cw[64][65];   // [word][col]
    const int tid  = threadIdx.x;
    const int base = blockIdx.x * 64;   // 98 blocks * 64 words = NWRD
    for (int e = tid; e < 4096; e += 256) {
        const int w = e >> 6, col = e & 63;
        cw[w][col] = g_t3[(size_t)(base + w) * 64 + col];
    }
    __syncthreads();
    if (tid < 64) {
        int cnt = 0;
        #pragma unroll 8
        for (int w = 0; w < 64; w++) cnt += __popc(cw[w][tid]);
        atomicAdd(&g_n3[tid], cnt);
    }
    for (int e = tid; e < 4096; e += 256) {
        const int i = e >> 6, j = e & 63;
        if (i < j) {
            int d = 0;
            #pragma unroll 8
            for (int w = 0; w < 64; w++) d += __popc(cw[w][i] ^ cw[w][j]);
            atomicAdd(&g_G[e], d);
        }
    }
}

// ---------------- K5: conv3 stats from gram -> BN3 affine ----------------
__global__ void k5_fin3(const float* __restrict__ g3, const float* __restrict__ b3) {
    const int c = blockIdx.x;     // 256 blocks x 64 threads
    const int i = threadIdx.x;
    const u64 w = g_w3b[c];
    const int wi = ((int)((w >> i) & 1ull)) * 2 - 1;

    int inner = 0;
    #pragma unroll 8
    for (int j = 0; j < 64; j++) {
        const int wj = ((int)((w >> j) & 1ull)) * 2 - 1;
        int gij;
        if (i == j) gij = NPIX;
        else        gij = NPIX - 2 * g_G[(i < j) ? (i * 64 + j) : (j * 64 + i)];
        inner += wj * gij;
    }
    int c_sq = wi * inner;
    int c_s  = wi * (2 * g_n3[i] - NPIX);

    __shared__ int s_sq[2], s_s[2];
    int rsq = __reduce_add_sync(0xFFFFFFFFu, c_sq);
    int rs  = __reduce_add_sync(0xFFFFFFFFu, c_s);
    if ((i & 31) == 0) { s_sq[i >> 5] = rsq; s_s[i >> 5] = rs; }
    __syncthreads();
    if (i == 0) {
        long long ssq = (long long)s_sq[0] + s_sq[1];
        long long ss  = (long long)s_s[0]  + s_s[1];
        double m   = (double)ss / CNTD;
        double var = (double)ssq / CNTD - m * m;
        double r   = rsqrt(var + EPSD);
        double A   = (double)g3[c] * r;
        g_A3[c] = (float)A;
        g_B3[c] = (float)((double)b3[c] - A * m);
    }
}

// ---------------- K6: conv3 recompute + BN3 + residual + hardtanh ----------------
__global__ __launch_bounds__(256) void k6_final(const float* __restrict__ x,
                                                float* __restrict__ out) {
    __shared__ u64 w3s[8];
    __shared__ float As[8], Bs[8];
    const int tid = threadIdx.x;
    const int cg  = blockIdx.y;          // 32 channel groups of 8
    if (tid < 8) {
        w3s[tid] = g_w3b[cg * 8 + tid];
        As[tid]  = g_A3[cg * 8 + tid];
        Bs[tid]  = g_B3[cg * 8 + tid];
    }
    __syncthreads();

    const int q  = blockIdx.x * 256 + tid;   // NQUAD
    const int n  = q / 784;
    const int hw = (q - n * 784) * 4;
    ulonglong4 a = g_a2[q];
    u64 av0 = a.x, av1 = a.y, av2 = a.z, av3 = a.w;

    const size_t base = ((size_t)n * CIN + (size_t)cg * 8) * HW + hw;
    #pragma unroll
    for (int k = 0; k < 8; k++) {
        const u64 wv = w3s[k];
        const float A = As[k], B = Bs[k];
        float4 xv = *reinterpret_cast<const float4*>(x + base + (size_t)k * HW);
        float4 o;
        o.x = fminf(fmaxf(fmaf(A, (float)(64 - 2 * __popcll(av0 ^ wv)), B) + xv.x, -1.f), 1.f);
        o.y = fminf(fmaxf(fmaf(A, (float)(64 - 2 * __popcll(av1 ^ wv)), B) + xv.y, -1.f), 1.f);
        o.z = fminf(fmaxf(fmaf(A, (float)(64 - 2 * __popcll(av2 ^ wv)), B) + xv.z, -1.f), 1.f);
        o.w = fminf(fmaxf(fmaf(A, (float)(64 - 2 * __popcll(av3 ^ wv)), B) + xv.w, -1.f), 1.f);
        *reinterpret_cast<float4*>(out + base + (size_t)k * HW) = o;
    }
}

extern "C" void kernel_launch(void* const* d_in, const int* in_sizes, int n_in,
                              void* d_out, int out_size) {
    const float* x  = (const float*)d_in[0];
    const float* w1 = (const float*)d_in[1];
    const float* w2 = (const float*)d_in[2];
    const float* w3 = (const float*)d_in[3];
    const float* g1 = (const float*)d_in[4];
    const float* b1 = (const float*)d_in[5];
    const float* g2 = (const float*)d_in[6];
    const float* b2 = (const float*)d_in[7];
    const float* g3 = (const float*)d_in[8];
    const float* b3 = (const float*)d_in[9];
    float* out = (float*)d_out;

    k0_init<<<1, 576>>>(w1, w2, w3);
    k1_conv1<<<392, 128>>>(x);
    k2_bnpack1<<<784, 256>>>(g1, b1);
    k3_conv2<<<896, 256>>>();
    k4_pack2<<<784, 256>>>(g2, b2);
    k4g_gram<<<98, 256>>>();
    k5_fin3<<<256, 64>>>(g3, b3);
    dim3 g6(196, 32);
    k6_final<<<g6, 256>>>(x, out);
}

// round 7
// speedup vs baseline: 1.0135x; 1.0135x over previous
#include <cuda_runtime.h>
#include <cstdint>

typedef unsigned long long u64;
typedef unsigned int u32;

#define NB    64
#define CIN   256
#define HH    56
#define WW    56
#define HW    3136
#define NPIX  200704   // NB*HW
#define NQUAD 50176    // NPIX/4
#define NPAIR 100352   // NPIX/2
#define NWRD  6272     // NPIX/32
#define CNTD  200704.0
#define EPSD  1e-5
#define PADW  58
#define PADHW 3364     // 58*58

// ---------------- static device scratch ----------------
__device__ u64  g_w1b[64 * 4];
__device__ u64  g_w2b[64 * 9];
__device__ u64  g_w3b[256];
__device__ int  g_ctab[9 * 64];       // border-pattern corrections for conv2
__device__ int4 g_s1v[8 * NPIX];      // conv1 outputs int16, [group][pixel]
__device__ short g_s2[NPIX * 64];     // conv2 outputs int16, [pixel][ch]
__device__ u64  g_a1p[NB * PADHW];    // conv2 input bits, zero halo
__device__ ulonglong4 g_a2[NQUAD];    // conv3 input bits (pixel-major u64)
__device__ u32  g_t3[NWRD * 64];      // transposed conv3 input bits: [pixword][bit]
__device__ int  g_G[4096];            // gram xor-popc, upper triangle i<j
__device__ int  g_n3[64];             // per-bit set counts
__device__ long long g_sum1[64], g_ss1[64];
__device__ long long g_sum2[64], g_ss2[64];
__device__ float g_A3[256], g_B3[256];

// ---------------- K0: zero scratch + pack weights + border table ----------------
__global__ void k0_init(const float* __restrict__ w1,
                        const float* __restrict__ w2,
                        const float* __restrict__ w3) {
    const int t = threadIdx.x;   // 576 threads
    if (t < 64) {
        u64 wd0 = 0, wd1 = 0, wd2 = 0, wd3 = 0;
        const float* wp = w1 + t * 256;
        #pragma unroll 8
        for (int c = 0; c < 64; c++) wd0 |= (u64)(wp[c]       > 0.f) << c;
        #pragma unroll 8
        for (int c = 0; c < 64; c++) wd1 |= (u64)(wp[c + 64]  > 0.f) << c;
        #pragma unroll 8
        for (int c = 0; c < 64; c++) wd2 |= (u64)(wp[c + 128] > 0.f) << c;
        #pragma unroll 8
        for (int c = 0; c < 64; c++) wd3 |= (u64)(wp[c + 192] > 0.f) << c;
        g_w1b[t * 4 + 0] = wd0; g_w1b[t * 4 + 1] = wd1;
        g_w1b[t * 4 + 2] = wd2; g_w1b[t * 4 + 3] = wd3;
        g_sum1[t] = 0; g_ss1[t] = 0; g_sum2[t] = 0; g_ss2[t] = 0;
        g_n3[t] = 0;
    }
    {   // w2 OIHW (64,64,3,3)
        const int co = t / 9, tap = t - co * 9;
        u64 wd = 0;
        #pragma unroll 8
        for (int ci = 0; ci < 64; ci++)
            wd |= (u64)(w2[(co * 64 + ci) * 9 + tap] > 0.f) << ci;
        g_w2b[t] = wd;
    }
    if (t < 256) {
        u64 wd = 0;
        #pragma unroll 8
        for (int ci = 0; ci < 64; ci++)
            wd |= (u64)(w3[t * 64 + ci] > 0.f) << ci;
        g_w3b[t] = wd;
    }
    for (int i = t; i < 4096; i += 576) g_G[i] = 0;
    __syncthreads();
    // Border correction table: what a zero halo word wrongly contributes.
    {
        const int pid = t / 64, co = t - pid * 64;  // pid<9
        const int rowc = pid / 3, colc = pid - rowc * 3;
        int corr = 0;
        #pragma unroll
        for (int tap = 0; tap < 9; tap++) {
            const int r = tap / 3, c = tap - r * 3;
            bool inval = (rowc == 1 && r == 0) || (rowc == 2 && r == 2) ||
                         (colc == 1 && c == 0) || (colc == 2 && c == 2);
            if (inval) corr += 64 - 2 * __popcll(g_w2b[co * 9 + tap]);
        }
        g_ctab[t] = corr;
    }
}

// ---------------- K1: pack x (2 px/thread, float2), conv1, stats ----------------
__global__ __launch_bounds__(256) void k1_conv1(const float* __restrict__ x) {
    __shared__ u64 w1s[256];
    __shared__ int ssum[64], sss[64];
    const int tid = threadIdx.x;
    if (tid < 64) { ssum[tid] = 0; sss[tid] = 0; }
    w1s[tid] = g_w1b[tid];
    __syncthreads();

    const int q  = blockIdx.x * 256 + tid;   // 392*256 = NPAIR
    const int n  = q / 1568;
    const int hw = (q - n * 1568) * 2;
    const float* xp = x + (size_t)n * CIN * HW + hw;

    u64 v[2][4];   // [pixel][word]
    #pragma unroll
    for (int wi = 0; wi < 4; wi++) {
        u64 b0 = 0, b1 = 0;
        #pragma unroll 16
        for (int c = 0; c < 64; c++) {
            float2 xv = *reinterpret_cast<const float2*>(xp + (size_t)(wi * 64 + c) * HW);
            b0 |= (u64)(xv.x > 0.f) << c;
            b1 |= (u64)(xv.y > 0.f) << c;
        }
        v[0][wi] = b0; v[1][wi] = b1;
    }

    const int lane = tid & 31;

    #pragma unroll 1
    for (int g = 0; g < 8; g++) {
        int pk[2][4];   // [pixel][jj]
        #pragma unroll
        for (int jj = 0; jj < 4; jj++) {
            int sv[2][2];
            #pragma unroll
            for (int k = 0; k < 2; k++) {
                const int co = g * 8 + jj * 2 + k;
                const u64* wq = &w1s[co * 4];
                const u64 q0 = wq[0], q1 = wq[1], q2 = wq[2], q3 = wq[3];
                int stot = 0, qtot = 0;
                #pragma unroll
                for (int j = 0; j < 2; j++) {
                    int d = __popcll(v[j][0] ^ q0) + __popcll(v[j][1] ^ q1)
                          + __popcll(v[j][2] ^ q2) + __popcll(v[j][3] ^ q3);
                    int s = 256 - 2 * d;
                    sv[j][k] = s; stot += s; qtot += s * s;
                }
                int rs = __reduce_add_sync(0xFFFFFFFFu, stot);
                int rq = __reduce_add_sync(0xFFFFFFFFu, qtot);
                if (lane == 0) { atomicAdd(&ssum[co], rs); atomicAdd(&sss[co], rq); }
            }
            #pragma unroll
            for (int j = 0; j < 2; j++)
                pk[j][jj] = (sv[j][0] & 0xFFFF) | (sv[j][1] << 16);
        }
        #pragma unroll
        for (int j = 0; j < 2; j++)
            g_s1v[(size_t)g * NPIX + 2 * q + j] = make_int4(pk[j][0], pk[j][1], pk[j][2], pk[j][3]);
    }
    __syncthreads();
    if (tid < 64) {
        atomicAdd((u64*)&g_sum1[tid], (u64)(long long)ssum[tid]);
        atomicAdd((u64*)&g_ss1[tid],  (u64)(long long)sss[tid]);
    }
}

// ---------------- K2: BN1 threshold -> padded conv2 input bits ----------------
__global__ __launch_bounds__(256) void k2_bnpack1(const float* __restrict__ g1,
                                                  const float* __restrict__ b1) {
    __shared__ float As[64], Bs[64];
    const int tid = threadIdx.x;
    if (tid < 64) {
        double m   = (double)g_sum1[tid] / CNTD;
        double var = (double)g_ss1[tid] / CNTD - m * m;
        double r   = rsqrt(var + EPSD);
        double A   = (double)g1[tid] * r;
        As[tid] = (float)A;
        Bs[tid] = (float)((double)b1[tid] - A * m);
    }
    __syncthreads();
    const int p = blockIdx.x * 256 + tid;
    u64 v = 0;
    #pragma unroll
    for (int g = 0; g < 8; g++) {
        int4 q = g_s1v[(size_t)g * NPIX + p];
        int arr[4] = {q.x, q.y, q.z, q.w};
        #pragma unroll
        for (int k = 0; k < 4; k++) {
            const int co = g * 8 + k * 2;
            float lo = (float)(short)arr[k];
            float hi = (float)(short)(arr[k] >> 16);
            v |= (u64)(fmaf(As[co],     lo, Bs[co])     > 0.f) << co;
            v |= (u64)(fmaf(As[co + 1], hi, Bs[co + 1]) > 0.f) << (co + 1);
        }
    }
    const int n  = p / HW;
    const int hw = p - n * HW;
    const int h  = hw / WW;
    const int w  = hw - h * WW;
    g_a1p[(size_t)n * PADHW + (size_t)(h + 1) * PADW + (w + 1)] = v;
}

// ---------------- K3: conv2 (3x3, pad 1) + stats; column-partial formulation ----------------
// Warp = (row, channel-half). Lane = channel (9 weights in regs).
// Per padded input column pc compute fL/fM/fR once (3 popc each against the
// tap-column weight sets); output(w) = fL(w) + fM(w+1) + fR(w+2).
__global__ __launch_bounds__(256) void k3_conv2() {
    __shared__ int bsum[64], bsq[64];
    const int tid  = threadIdx.x;
    const int wid  = tid >> 5;
    const int lane = tid & 31;
    if (tid < 64) { bsum[tid] = 0; bsq[tid] = 0; }
    __syncthreads();

    const int job  = blockIdx.x * 8 + wid;   // 896 blocks * 8 = 7168 jobs
    const int half = job & 1;
    const int row  = job >> 1;               // 0..3583
    const int n    = row / HH;
    const int h    = row - n * HH;
    const int ch   = half * 32 + lane;

    u64 wv[9];
    #pragma unroll
    for (int t = 0; t < 9; t++) wv[t] = g_w2b[ch * 9 + t];

    const int rowc = (h == 0) ? 1 : ((h == HH - 1) ? 2 : 0);
    const int corr_m = g_ctab[(rowc * 3 + 0) * 64 + ch];
    const int corr_l = g_ctab[(rowc * 3 + 1) * 64 + ch];
    const int corr_r = g_ctab[(rowc * 3 + 2) * 64 + ch];

    const u64* r0 = g_a1p + (size_t)n * PADHW + (size_t)h * PADW;
    const u64* r1 = r0 + PADW;
    const u64* r2 = r1 + PADW;

    int pL[6], pM[6], pR[6];
    // prologue: partials for padded cols 0,1
    #pragma unroll
    for (int sl = 0; sl < 2; sl++) {
        u64 a0 = __ldg(r0 + sl), a1 = __ldg(r1 + sl), a2 = __ldg(r2 + sl);
        pL[sl] = __popcll(a0 ^ wv[0]) + __popcll(a1 ^ wv[3]) + __popcll(a2 ^ wv[6]);
        pM[sl] = __popcll(a0 ^ wv[1]) + __popcll(a1 ^ wv[4]) + __popcll(a2 ^ wv[7]);
        pR[sl] = __popcll(a0 ^ wv[2]) + __popcll(a1 ^ wv[5]) + __popcll(a2 ^ wv[8]);
    }

    short* orow = g_s2 + (size_t)(n * HW + h * WW) * 64 + ch;
    int accs = 0, accq = 0;

    #pragma unroll 1
    for (int c = 0; c < 14; c++) {
        const int base = c * 4;
        u64 la0[4], la1[4], la2[4];
        #pragma unroll
        for (int j = 0; j < 4; j++) {
            la0[j] = __ldg(r0 + base + 2 + j);
            la1[j] = __ldg(r1 + base + 2 + j);
            la2[j] = __ldg(r2 + base + 2 + j);
        }
        #pragma unroll
        for (int j = 0; j < 4; j++) {
            pL[2 + j] = __popcll(la0[j] ^ wv[0]) + __popcll(la1[j] ^ wv[3]) + __popcll(la2[j] ^ wv[6]);
            pM[2 + j] = __popcll(la0[j] ^ wv[1]) + __popcll(la1[j] ^ wv[4]) + __popcll(la2[j] ^ wv[7]);
            pR[2 + j] = __popcll(la0[j] ^ wv[2]) + __popcll(la1[j] ^ wv[5]) + __popcll(la2[j] ^ wv[8]);
        }
        #pragma unroll
        for (int j = 0; j < 4; j++) {
            const int w = base + j;
            int d = pL[j] + pM[j + 1] + pR[j + 2];
            const int corr = (w == 0) ? corr_l : ((w == WW - 1) ? corr_r : corr_m);
            int s = 576 - 2 * d - corr;
            accs += s; accq += s * s;
            orow[(size_t)w * 64] = (short)s;
        }
        pL[0] = pL[4]; pL[1] = pL[5];
        pM[0] = pM[4]; pM[1] = pM[5];
        pR[0] = pR[4]; pR[1] = pR[5];
    }

    atomicAdd(&bsum[ch], accs);
    atomicAdd(&bsq[ch],  accq);
    __syncthreads();
    if (tid < 64) {
        atomicAdd((u64*)&g_sum2[tid], (u64)(long long)bsum[tid]);
        atomicAdd((u64*)&g_ss2[tid],  (u64)(long long)bsq[tid]);
    }
}

// ---------------- K4: BN2 threshold -> conv3 bits + ballot transpose ----------------
__global__ __launch_bounds__(256) void k4_pack2(const float* __restrict__ g2,
                                                const float* __restrict__ b2) {
    __shared__ float As[64], Bs[64];
    const int tid = threadIdx.x;
    if (tid < 64) {
        double m   = (double)g_sum2[tid] / CNTD;
        double var = (double)g_ss2[tid] / CNTD - m * m;
        double r   = rsqrt(var + EPSD);
        double A   = (double)g2[tid] * r;
        As[tid] = (float)A;
        Bs[tid] = (float)((double)b2[tid] - A * m);
    }
    __syncthreads();

    const int p = blockIdx.x * 256 + tid;   // 784 blocks
    const int4* sp = reinterpret_cast<const int4*>(g_s2 + (size_t)p * 64);
    u64 v = 0;
    #pragma unroll
    for (int g = 0; g < 8; g++) {
        int4 qq = sp[g];
        int arr[4] = {qq.x, qq.y, qq.z, qq.w};
        #pragma unroll
        for (int k = 0; k < 4; k++) {
            const int co = g * 8 + k * 2;
            float lo = (float)(short)arr[k];
            float hi = (float)(short)(arr[k] >> 16);
            v |= (u64)(fmaf(As[co],     lo, Bs[co])     > 0.f) << co;
            v |= (u64)(fmaf(As[co + 1], hi, Bs[co + 1]) > 0.f) << (co + 1);
        }
    }
    reinterpret_cast<u64*>(g_a2)[p] = v;

    // ballot transpose: warp's 32 pixels x 64 bits -> 64 u32 column words
    const int lane = tid & 31;
    const int gw   = p >> 5;
    u32 r0 = 0, r1 = 0;
    #pragma unroll
    for (int b = 0; b < 64; b++) {
        u32 bl = __ballot_sync(0xFFFFFFFFu, (u32)((v >> b) & 1ull));
        if (b == lane)      r0 = bl;
        if (b == lane + 32) r1 = bl;
    }
    g_t3[(size_t)gw * 64 + lane]      = r0;
    g_t3[(size_t)gw * 64 + 32 + lane] = r1;
}

// ---------------- K4g: gram matrix of conv3 input bit-columns ----------------
__global__ __launch_bounds__(256) void k4g_gram() {
    __shared__ u32 cw[64][65];   // [word][col]
    const int tid  = threadIdx.x;
    const int base = blockIdx.x * 64;   // 98 blocks * 64 words = NWRD
    for (int e = tid; e < 4096; e += 256) {
        const int w = e >> 6, col = e & 63;
        cw[w][col] = g_t3[(size_t)(base + w) * 64 + col];
    }
    __syncthreads();
    if (tid < 64) {
        int cnt = 0;
        #pragma unroll 8
        for (int w = 0; w < 64; w++) cnt += __popc(cw[w][tid]);
        atomicAdd(&g_n3[tid], cnt);
    }
    for (int e = tid; e < 4096; e += 256) {
        const int i = e >> 6, j = e & 63;
        if (i < j) {
            int d = 0;
            #pragma unroll 8
            for (int w = 0; w < 64; w++) d += __popc(cw[w][i] ^ cw[w][j]);
            atomicAdd(&g_G[e], d);
        }
    }
}

// ---------------- K5: conv3 stats from gram -> BN3 affine ----------------
__global__ void k5_fin3(const float* __restrict__ g3, const float* __restrict__ b3) {
    const int c = blockIdx.x;     // 256 blocks x 64 threads
    const int i = threadIdx.x;
    const u64 w = g_w3b[c];
    const int wi = ((int)((w >> i) & 1ull)) * 2 - 1;

    int inner = 0;
    #pragma unroll 8
    for (int j = 0; j < 64; j++) {
        const int wj = ((int)((w >> j) & 1ull)) * 2 - 1;
        int gij;
        if (i == j) gij = NPIX;
        else        gij = NPIX - 2 * g_G[(i < j) ? (i * 64 + j) : (j * 64 + i)];
        inner += wj * gij;
    }
    int c_sq = wi * inner;
    int c_s  = wi * (2 * g_n3[i] - NPIX);

    __shared__ int s_sq[2], s_s[2];
    int rsq = __reduce_add_sync(0xFFFFFFFFu, c_sq);
    int rs  = __reduce_add_sync(0xFFFFFFFFu, c_s);
    if ((i & 31) == 0) { s_sq[i >> 5] = rsq; s_s[i >> 5] = rs; }
    __syncthreads();
    if (i == 0) {
        long long ssq = (long long)s_sq[0] + s_sq[1];
        long long ss  = (long long)s_s[0]  + s_s[1];
        double m   = (double)ss / CNTD;
        double var = (double)ssq / CNTD - m * m;
        double r   = rsqrt(var + EPSD);
        double A   = (double)g3[c] * r;
        g_A3[c] = (float)A;
        g_B3[c] = (float)((double)b3[c] - A * m);
    }
}

// ---------------- K6: conv3 recompute + BN3 + residual + hardtanh ----------------
__global__ __launch_bounds__(256) void k6_final(const float* __restrict__ x,
                                                float* __restrict__ out) {
    __shared__ u64 w3s[8];
    __shared__ float As[8], Bs[8];
    const int tid = threadIdx.x;
    const int cg  = blockIdx.y;          // 32 channel groups of 8
    if (tid < 8) {
        w3s[tid] = g_w3b[cg * 8 + tid];
        As[tid]  = g_A3[cg * 8 + tid];
        Bs[tid]  = g_B3[cg * 8 + tid];
    }
    __syncthreads();

    const int q  = blockIdx.x * 256 + tid;   // NQUAD
    const int n  = q / 784;
    const int hw = (q - n * 784) * 4;
    ulonglong4 a = g_a2[q];
    u64 av0 = a.x, av1 = a.y, av2 = a.z, av3 = a.w;

    const size_t base = ((size_t)n * CIN + (size_t)cg * 8) * HW + hw;
    #pragma unroll
    for (int k = 0; k < 8; k++) {
        const u64 wv = w3s[k];
        const float A = As[k], B = Bs[k];
        float4 xv = *reinterpret_cast<const float4*>(x + base + (size_t)k * HW);
        float4 o;
        o.x = fminf(fmaxf(fmaf(A, (float)(64 - 2 * __popcll(av0 ^ wv)), B) + xv.x, -1.f), 1.f);
        o.y = fminf(fmaxf(fmaf(A, (float)(64 - 2 * __popcll(av1 ^ wv)), B) + xv.y, -1.f), 1.f);
        o.z = fminf(fmaxf(fmaf(A, (float)(64 - 2 * __popcll(av2 ^ wv)), B) + xv.z, -1.f), 1.f);
        o.w = fminf(fmaxf(fmaf(A, (float)(64 - 2 * __popcll(av3 ^ wv)), B) + xv.w, -1.f), 1.f);
        *reinterpret_cast<float4*>(out + base + (size_t)k * HW) = o;
    }
}

extern "C" void kernel_launch(void* const* d_in, const int* in_sizes, int n_in,
                              void* d_out, int out_size) {
    const float* x  = (const float*)d_in[0];
    const float* w1 = (const float*)d_in[1];
    const float* w2 = (const float*)d_in[2];
    const float* w3 = (const float*)d_in[3];
    const float* g1 = (const float*)d_in[4];
    const float* b1 = (const float*)d_in[5];
    const float* g2 = (const float*)d_in[6];
    const float* b2 = (const float*)d_in[7];
    const float* g3 = (const float*)d_in[8];
    const float* b3 = (const float*)d_in[9];
    float* out = (float*)d_out;

    k0_init<<<1, 576>>>(w1, w2, w3);
    k1_conv1<<<392, 256>>>(x);
    k2_bnpack1<<<784, 256>>>(g1, b1);
    k3_conv2<<<896, 256>>>();
    k4_pack2<<<784, 256>>>(g2, b2);
    k4g_gram<<<98, 256>>>();
    k5_fin3<<<256, 64>>>(g3, b3);
    dim3 g6(196, 32);
    k6_final<<<g6, 256>>>(x, out);
}

// round 8
// speedup vs baseline: 1.0192x; 1.0056x over previous
#include <cuda_runtime.h>
#include <cstdint>

typedef unsigned long long u64;
typedef unsigned int u32;

#define NB    64
#define CIN   256
#define HH    56
#define WW    56
#define HW    3136
#define NPIX  200704   // NB*HW
#define NQUAD 50176    // NPIX/4
#define NPAIR 100352   // NPIX/2
#define NWRD  6272     // NPIX/32
#define CNTD  200704.0
#define EPSD  1e-5
#define PADW  58
#define PADHW 3364     // 58*58

// ---------------- static device scratch ----------------
__device__ u64  g_w1b[64 * 4];
__device__ u64  g_w2b[64 * 9];
__device__ u64  g_w3b[256];
__device__ int  g_ctab[9 * 64];       // border-pattern corrections for conv2
__device__ int4 g_s1v[8 * NPIX];      // conv1 outputs int16, [group][pixel]
__device__ short g_s2[NPIX * 64];     // conv2 outputs int16, [pixel][ch]
__device__ u64  g_a1p[NB * PADHW];    // conv2 input bits, zero halo
__device__ ulonglong4 g_a2[NQUAD];    // conv3 input bits (pixel-major u64)
__device__ u32  g_t3[NWRD * 64];      // transposed conv3 input bits: [pixword][bit]
__device__ int  g_G[4096];            // gram xor-popc, upper triangle i<j
__device__ int  g_n3[64];             // per-bit set counts
__device__ long long g_sum1[64], g_ss1[64];
__device__ long long g_sum2[64], g_ss2[64];
__device__ float g_A3[256], g_B3[256];

// ---------------- K0: zero scratch + pack weights + border table ----------------
__global__ void k0_init(const float* __restrict__ w1,
                        const float* __restrict__ w2,
                        const float* __restrict__ w3) {
    const int t = threadIdx.x;   // 576 threads
    if (t < 64) {
        u64 wd0 = 0, wd1 = 0, wd2 = 0, wd3 = 0;
        const float* wp = w1 + t * 256;
        #pragma unroll 8
        for (int c = 0; c < 64; c++) wd0 |= (u64)(wp[c]       > 0.f) << c;
        #pragma unroll 8
        for (int c = 0; c < 64; c++) wd1 |= (u64)(wp[c + 64]  > 0.f) << c;
        #pragma unroll 8
        for (int c = 0; c < 64; c++) wd2 |= (u64)(wp[c + 128] > 0.f) << c;
        #pragma unroll 8
        for (int c = 0; c < 64; c++) wd3 |= (u64)(wp[c + 192] > 0.f) << c;
        g_w1b[t * 4 + 0] = wd0; g_w1b[t * 4 + 1] = wd1;
        g_w1b[t * 4 + 2] = wd2; g_w1b[t * 4 + 3] = wd3;
        g_sum1[t] = 0; g_ss1[t] = 0; g_sum2[t] = 0; g_ss2[t] = 0;
        g_n3[t] = 0;
    }
    {   // w2 OIHW (64,64,3,3)
        const int co = t / 9, tap = t - co * 9;
        u64 wd = 0;
        #pragma unroll 8
        for (int ci = 0; ci < 64; ci++)
            wd |= (u64)(w2[(co * 64 + ci) * 9 + tap] > 0.f) << ci;
        g_w2b[t] = wd;
    }
    if (t < 256) {
        u64 wd = 0;
        #pragma unroll 8
        for (int ci = 0; ci < 64; ci++)
            wd |= (u64)(w3[t * 64 + ci] > 0.f) << ci;
        g_w3b[t] = wd;
    }
    for (int i = t; i < 4096; i += 576) g_G[i] = 0;
    __syncthreads();
    // Border correction table: what a zero halo word wrongly contributes.
    {
        const int pid = t / 64, co = t - pid * 64;  // pid<9
        const int rowc = pid / 3, colc = pid - rowc * 3;
        int corr = 0;
        #pragma unroll
        for (int tap = 0; tap < 9; tap++) {
            const int r = tap / 3, c = tap - r * 3;
            bool inval = (rowc == 1 && r == 0) || (rowc == 2 && r == 2) ||
                         (colc == 1 && c == 0) || (colc == 2 && c == 2);
            if (inval) corr += 64 - 2 * __popcll(g_w2b[co * 9 + tap]);
        }
        g_ctab[t] = corr;
    }
}

// ---------------- K1: pack x (2 px/thread, float2), conv1, stats ----------------
__global__ __launch_bounds__(256) void k1_conv1(const float* __restrict__ x) {
    __shared__ u64 w1s[256];
    __shared__ int ssum[64], sss[64];
    const int tid = threadIdx.x;
    if (tid < 64) { ssum[tid] = 0; sss[tid] = 0; }
    w1s[tid] = g_w1b[tid];
    __syncthreads();

    const int q  = blockIdx.x * 256 + tid;   // 392*256 = NPAIR
    const int n  = q / 1568;
    const int hw = (q - n * 1568) * 2;
    const float* xp = x + (size_t)n * CIN * HW + hw;

    u64 v[2][4];   // [pixel][word]
    #pragma unroll
    for (int wi = 0; wi < 4; wi++) {
        u64 b0 = 0, b1 = 0;
        #pragma unroll 16
        for (int c = 0; c < 64; c++) {
            float2 xv = *reinterpret_cast<const float2*>(xp + (size_t)(wi * 64 + c) * HW);
            b0 |= (u64)(xv.x > 0.f) << c;
            b1 |= (u64)(xv.y > 0.f) << c;
        }
        v[0][wi] = b0; v[1][wi] = b1;
    }

    const int lane = tid & 31;

    #pragma unroll 1
    for (int g = 0; g < 8; g++) {
        int pk[2][4];   // [pixel][jj]
        #pragma unroll
        for (int jj = 0; jj < 4; jj++) {
            int sv[2][2];
            #pragma unroll
            for (int k = 0; k < 2; k++) {
                const int co = g * 8 + jj * 2 + k;
                const u64* wq = &w1s[co * 4];
                const u64 q0 = wq[0], q1 = wq[1], q2 = wq[2], q3 = wq[3];
                int stot = 0, qtot = 0;
                #pragma unroll
                for (int j = 0; j < 2; j++) {
                    int d = __popcll(v[j][0] ^ q0) + __popcll(v[j][1] ^ q1)
                          + __popcll(v[j][2] ^ q2) + __popcll(v[j][3] ^ q3);
                    int s = 256 - 2 * d;
                    sv[j][k] = s; stot += s; qtot += s * s;
                }
                int rs = __reduce_add_sync(0xFFFFFFFFu, stot);
                int rq = __reduce_add_sync(0xFFFFFFFFu, qtot);
                if (lane == 0) { atomicAdd(&ssum[co], rs); atomicAdd(&sss[co], rq); }
            }
            #pragma unroll
            for (int j = 0; j < 2; j++)
                pk[j][jj] = (sv[j][0] & 0xFFFF) | (sv[j][1] << 16);
        }
        #pragma unroll
        for (int j = 0; j < 2; j++)
            g_s1v[(size_t)g * NPIX + 2 * q + j] = make_int4(pk[j][0], pk[j][1], pk[j][2], pk[j][3]);
    }
    __syncthreads();
    if (tid < 64) {
        atomicAdd((u64*)&g_sum1[tid], (u64)(long long)ssum[tid]);
        atomicAdd((u64*)&g_ss1[tid],  (u64)(long long)sss[tid]);
    }
}

// ---------------- K2: BN1 threshold -> padded conv2 input bits ----------------
__global__ __launch_bounds__(256) void k2_bnpack1(const float* __restrict__ g1,
                                                  const float* __restrict__ b1) {
    __shared__ float As[64], Bs[64];
    const int tid = threadIdx.x;
    if (tid < 64) {
        double m   = (double)g_sum1[tid] / CNTD;
        double var = (double)g_ss1[tid] / CNTD - m * m;
        double r   = rsqrt(var + EPSD);
        double A   = (double)g1[tid] * r;
        As[tid] = (float)A;
        Bs[tid] = (float)((double)b1[tid] - A * m);
    }
    __syncthreads();
    const int p = blockIdx.x * 256 + tid;
    u64 v = 0;
    #pragma unroll
    for (int g = 0; g < 8; g++) {
        int4 q = g_s1v[(size_t)g * NPIX + p];
        int arr[4] = {q.x, q.y, q.z, q.w};
        #pragma unroll
        for (int k = 0; k < 4; k++) {
            const int co = g * 8 + k * 2;
            float lo = (float)(short)arr[k];
            float hi = (float)(short)(arr[k] >> 16);
            v |= (u64)(fmaf(As[co],     lo, Bs[co])     > 0.f) << co;
            v |= (u64)(fmaf(As[co + 1], hi, Bs[co + 1]) > 0.f) << (co + 1);
        }
    }
    const int n  = p / HW;
    const int hw = p - n * HW;
    const int h  = hw / WW;
    const int w  = hw - h * WW;
    g_a1p[(size_t)n * PADHW + (size_t)(h + 1) * PADW + (w + 1)] = v;
}

// ---------------- K3: conv2 (3x3, pad 1) + stats; smem row staging ----------------
// Block = (batch n, 4 output rows). Cooperatively stage the 6 padded input
// rows into smem once (L2 -> smem), then 8 warps (4 rows x 2 channel-halves)
// compute entirely from LDS broadcasts (29-cyc latency, conflict-free).
__global__ __launch_bounds__(256) void k3_conv2() {
    __shared__ u64 tile[6 * 64];   // 6 padded rows, pitch 64 (58 used)
    __shared__ int bsum[64], bsq[64];
    const int tid  = threadIdx.x;
    const int wid  = tid >> 5;
    const int lane = tid & 31;
    if (tid < 64) { bsum[tid] = 0; bsq[tid] = 0; }

    const int blk = blockIdx.x;          // 896 = 64 n * 14 row-quads
    const int n   = blk / 14;
    const int h0  = (blk - n * 14) * 4;  // first output row of this quad

    // stage padded rows h0..h0+5 (they cover outputs h0..h0+3)
    const u64* src = g_a1p + (size_t)n * PADHW + (size_t)h0 * PADW;
    for (int i = tid; i < 384; i += 256) {
        const int r = i >> 6, c = i & 63;
        if (c < PADW) tile[r * 64 + c] = src[r * PADW + c];
    }
    __syncthreads();

    const int ro   = wid >> 1;           // 0..3: output row within quad
    const int h    = h0 + ro;
    const int half = wid & 1;
    const int ch   = half * 32 + lane;

    u64 wv[9];
    #pragma unroll
    for (int t = 0; t < 9; t++) wv[t] = g_w2b[ch * 9 + t];

    const int rowc = (h == 0) ? 1 : ((h == HH - 1) ? 2 : 0);
    const int corr_m = g_ctab[(rowc * 3 + 0) * 64 + ch];
    const int corr_l = g_ctab[(rowc * 3 + 1) * 64 + ch];
    const int corr_r = g_ctab[(rowc * 3 + 2) * 64 + ch];

    const u64* t0 = &tile[ro * 64];
    const u64* t1 = t0 + 64;
    const u64* t2 = t1 + 64;

    u64 a[3][6];
    a[0][0] = t0[0]; a[0][1] = t0[1];
    a[1][0] = t1[0]; a[1][1] = t1[1];
    a[2][0] = t2[0]; a[2][1] = t2[1];

    short* orow = g_s2 + (size_t)(n * HW + h * WW) * 64 + ch;
    int accs = 0, accq = 0;

    #pragma unroll 1
    for (int c = 0; c < 14; c++) {
        const int base = c * 4;
        #pragma unroll
        for (int j = 0; j < 4; j++) {
            a[0][2 + j] = t0[base + 2 + j];
            a[1][2 + j] = t1[base + 2 + j];
            a[2][2 + j] = t2[base + 2 + j];
        }
        #pragma unroll
        for (int j = 0; j < 4; j++) {
            const int w = base + j;
            int d = __popcll(a[0][j] ^ wv[0]) + __popcll(a[0][j+1] ^ wv[1]) + __popcll(a[0][j+2] ^ wv[2])
                  + __popcll(a[1][j] ^ wv[3]) + __popcll(a[1][j+1] ^ wv[4]) + __popcll(a[1][j+2] ^ wv[5])
                  + __popcll(a[2][j] ^ wv[6]) + __popcll(a[2][j+1] ^ wv[7]) + __popcll(a[2][j+2] ^ wv[8]);
            const int corr = (w == 0) ? corr_l : ((w == WW - 1) ? corr_r : corr_m);
            int s = 576 - 2 * d - corr;
            accs += s; accq += s * s;
            orow[(size_t)w * 64] = (short)s;
        }
        #pragma unroll
        for (int r = 0; r < 3; r++) { a[r][0] = a[r][4]; a[r][1] = a[r][5]; }
    }

    atomicAdd(&bsum[ch], accs);
    atomicAdd(&bsq[ch],  accq);
    __syncthreads();
    if (tid < 64) {
        atomicAdd((u64*)&g_sum2[tid], (u64)(long long)bsum[tid]);
        atomicAdd((u64*)&g_ss2[tid],  (u64)(long long)bsq[tid]);
    }
}

// ---------------- K4: BN2 threshold -> conv3 bits + ballot transpose ----------------
__global__ __launch_bounds__(256) void k4_pack2(const float* __restrict__ g2,
                                                const float* __restrict__ b2) {
    __shared__ float As[64], Bs[64];
    const int tid = threadIdx.x;
    if (tid < 64) {
        double m   = (double)g_sum2[tid] / CNTD;
        double var = (double)g_ss2[tid] / CNTD - m * m;
        double r   = rsqrt(var + EPSD);
        double A   = (double)g2[tid] * r;
        As[tid] = (float)A;
        Bs[tid] = (float)((double)b2[tid] - A * m);
    }
    __syncthreads();

    const int p = blockIdx.x * 256 + tid;   // 784 blocks
    const int4* sp = reinterpret_cast<const int4*>(g_s2 + (size_t)p * 64);
    u64 v = 0;
    #pragma unroll
    for (int g = 0; g < 8; g++) {
        int4 qq = sp[g];
        int arr[4] = {qq.x, qq.y, qq.z, qq.w};
        #pragma unroll
        for (int k = 0; k < 4; k++) {
            const int co = g * 8 + k * 2;
            float lo = (float)(short)arr[k];
            float hi = (float)(short)(arr[k] >> 16);
            v |= (u64)(fmaf(As[co],     lo, Bs[co])     > 0.f) << co;
            v |= (u64)(fmaf(As[co + 1], hi, Bs[co + 1]) > 0.f) << (co + 1);
        }
    }
    reinterpret_cast<u64*>(g_a2)[p] = v;

    // ballot transpose: warp's 32 pixels x 64 bits -> 64 u32 column words
    const int lane = tid & 31;
    const int gw   = p >> 5;
    u32 r0 = 0, r1 = 0;
    #pragma unroll
    for (int b = 0; b < 64; b++) {
        u32 bl = __ballot_sync(0xFFFFFFFFu, (u32)((v >> b) & 1ull));
        if (b == lane)      r0 = bl;
        if (b == lane + 32) r1 = bl;
    }
    g_t3[(size_t)gw * 64 + lane]      = r0;
    g_t3[(size_t)gw * 64 + 32 + lane] = r1;
}

// ---------------- K4g: gram matrix of conv3 input bit-columns ----------------
__global__ __launch_bounds__(256) void k4g_gram() {
    __shared__ u32 cw[64][65];   // [word][col]
    const int tid  = threadIdx.x;
    const int base = blockIdx.x * 64;   // 98 blocks * 64 words = NWRD
    for (int e = tid; e < 4096; e += 256) {
        const int w = e >> 6, col = e & 63;
        cw[w][col] = g_t3[(size_t)(base + w) * 64 + col];
    }
    __syncthreads();
    if (tid < 64) {
        int cnt = 0;
        #pragma unroll 8
        for (int w = 0; w < 64; w++) cnt += __popc(cw[w][tid]);
        atomicAdd(&g_n3[tid], cnt);
    }
    for (int e = tid; e < 4096; e += 256) {
        const int i = e >> 6, j = e & 63;
        if (i < j) {
            int d = 0;
            #pragma unroll 8
            for (int w = 0; w < 64; w++) d += __popc(cw[w][i] ^ cw[w][j]);
            atomicAdd(&g_G[e], d);
        }
    }
}

// ---------------- K5: conv3 stats from gram -> BN3 affine ----------------
__global__ void k5_fin3(const float* __restrict__ g3, const float* __restrict__ b3) {
    const int c = blockIdx.x;     // 256 blocks x 64 threads
    const int i = threadIdx.x;
    const u64 w = g_w3b[c];
    const int wi = ((int)((w >> i) & 1ull)) * 2 - 1;

    int inner = 0;
    #pragma unroll 8
    for (int j = 0; j < 64; j++) {
        const int wj = ((int)((w >> j) & 1ull)) * 2 - 1;
        int gij;
        if (i == j) gij = NPIX;
        else        gij = NPIX - 2 * g_G[(i < j) ? (i * 64 + j) : (j * 64 + i)];
        inner += wj * gij;
    }
    int c_sq = wi * inner;
    int c_s  = wi * (2 * g_n3[i] - NPIX);

    __shared__ int s_sq[2], s_s[2];
    int rsq = __reduce_add_sync(0xFFFFFFFFu, c_sq);
    int rs  = __reduce_add_sync(0xFFFFFFFFu, c_s);
    if ((i & 31) == 0) { s_sq[i >> 5] = rsq; s_s[i >> 5] = rs; }
    __syncthreads();
    if (i == 0) {
        long long ssq = (long long)s_sq[0] + s_sq[1];
        long long ss  = (long long)s_s[0]  + s_s[1];
        double m   = (double)ss / CNTD;
        double var = (double)ssq / CNTD - m * m;
        double r   = rsqrt(var + EPSD);
        double A   = (double)g3[c] * r;
        g_A3[c] = (float)A;
        g_B3[c] = (float)((double)b3[c] - A * m);
    }
}

// ---------------- K6: conv3 recompute + BN3 + residual + hardtanh ----------------
__global__ __launch_bounds__(256) void k6_final(const float* __restrict__ x,
                                                float* __restrict__ out) {
    __shared__ u64 w3s[8];
    __shared__ float As[8], Bs[8];
    const int tid = threadIdx.x;
    const int cg  = blockIdx.y;          // 32 channel groups of 8
    if (tid < 8) {
        w3s[tid] = g_w3b[cg * 8 + tid];
        As[tid]  = g_A3[cg * 8 + tid];
        Bs[tid]  = g_B3[cg * 8 + tid];
    }
    __syncthreads();

    const int q  = blockIdx.x * 256 + tid;   // NQUAD
    const int n  = q / 784;
    const int hw = (q - n * 784) * 4;
    ulonglong4 a = g_a2[q];
    u64 av0 = a.x, av1 = a.y, av2 = a.z, av3 = a.w;

    const size_t base = ((size_t)n * CIN + (size_t)cg * 8) * HW + hw;
    #pragma unroll
    for (int k = 0; k < 8; k++) {
        const u64 wv = w3s[k];
        const float A = As[k], B = Bs[k];
        float4 xv = *reinterpret_cast<const float4*>(x + base + (size_t)k * HW);
        float4 o;
        o.x = fminf(fmaxf(fmaf(A, (float)(64 - 2 * __popcll(av0 ^ wv)), B) + xv.x, -1.f), 1.f);
        o.y = fminf(fmaxf(fmaf(A, (float)(64 - 2 * __popcll(av1 ^ wv)), B) + xv.y, -1.f), 1.f);
        o.z = fminf(fmaxf(fmaf(A, (float)(64 - 2 * __popcll(av2 ^ wv)), B) + xv.z, -1.f), 1.f);
        o.w = fminf(fmaxf(fmaf(A, (float)(64 - 2 * __popcll(av3 ^ wv)), B) + xv.w, -1.f), 1.f);
        *reinterpret_cast<float4*>(out + base + (size_t)k * HW) = o;
    }
}

extern "C" void kernel_launch(void* const* d_in, const int* in_sizes, int n_in,
                              void* d_out, int out_size) {
    const float* x  = (const float*)d_in[0];
    const float* w1 = (const float*)d_in[1];
    const float* w2 = (const float*)d_in[2];
    const float* w3 = (const float*)d_in[3];
    const float* g1 = (const float*)d_in[4];
    const float* b1 = (const float*)d_in[5];
    const float* g2 = (const float*)d_in[6];
    const float* b2 = (const float*)d_in[7];
    const float* g3 = (const float*)d_in[8];
    const float* b3 = (const float*)d_in[9];
    float* out = (float*)d_out;

    k0_init<<<1, 576>>>(w1, w2, w3);
    k1_conv1<<<392, 256>>>(x);
    k2_bnpack1<<<784, 256>>>(g1, b1);
    k3_conv2<<<896, 256>>>();
    k4_pack2<<<784, 256>>>(g2, b2);
    k4g_gram<<<98, 256>>>();
    k5_fin3<<<256, 64>>>(g3, b3);
    dim3 g6(196, 32);
    k6_final<<<g6, 256>>>(x, out);
}

// round 9
// speedup vs baseline: 1.1034x; 1.0826x over previous
#include <cuda_runtime.h>
#include <cstdint>

typedef unsigned long long u64;
typedef unsigned int u32;

#define NB    64
#define CIN   256
#define HH    56
#define WW    56
#define HW    3136
#define NPIX  200704   // NB*HW
#define NQUAD 50176    // NPIX/4
#define NPAIR 100352   // NPIX/2
#define NWRD  6272     // NPIX/32
#define CNTD  200704.0
#define EPSD  1e-5
#define PADW  58
#define PADHW 3364     // 58*58

// ---------------- static device scratch ----------------
__device__ u64  g_w1b[64 * 4];
__device__ u64  g_w2b[64 * 9];
__device__ u64  g_w3b[256];
__device__ int  g_ctab[9 * 64];       // border-pattern corrections for conv2
__device__ int4 g_s1v[8 * NPIX];      // conv1 outputs int16, [group][pixel]
__device__ short g_s2[NPIX * 64];     // conv2 outputs int16, [pixel][ch]
__device__ u64  g_a1p[NB * PADHW];    // conv2 input bits, zero halo
__device__ ulonglong4 g_a2[NQUAD];    // conv3 input bits (pixel-major u64)
__device__ u32  g_t3[NWRD * 64];      // transposed conv3 input bits: [pixword][bit]
__device__ int  g_G[4096];            // gram xor-popc, upper triangle i<j
__device__ int  g_n3[64];             // per-bit set counts
__device__ long long g_sum1[64], g_ss1[64];
__device__ long long g_sum2[64], g_ss2[64];
__device__ float g_A3[256], g_B3[256];

// ---------------- K0: multi-block init; block b owns conv2-channel b ----------------
__global__ __launch_bounds__(64) void k0_init(const float* __restrict__ w1,
                                              const float* __restrict__ w2,
                                              const float* __restrict__ w3) {
    __shared__ float w2s[576];
    __shared__ u64 w2bits[9];
    const int b = blockIdx.x;    // 64 blocks
    const int t = threadIdx.x;   // 64 threads

    // stage w2 slice for co=b (576 consecutive floats), coalesced
    for (int i = t; i < 576; i += 64) w2s[i] = w2[b * 576 + i];

    // w1 pack: channel b = 4 words of 64 bits
    if (t < 4) {
        u64 wd = 0;
        const float* wp = w1 + b * 256 + t * 64;
        #pragma unroll 8
        for (int c = 0; c < 64; c++) wd |= (u64)(wp[c] > 0.f) << c;
        g_w1b[b * 4 + t] = wd;
    }
    // w3 pack: channels 4b..4b+3
    if (t >= 4 && t < 8) {
        const int ch = b * 4 + (t - 4);
        u64 wd = 0;
        const float* wp = w3 + ch * 64;
        #pragma unroll 8
        for (int c = 0; c < 64; c++) wd |= (u64)(wp[c] > 0.f) << c;
        g_w3b[ch] = wd;
    }
    // zero scratch
    g_G[b * 64 + t] = 0;
    if (b == 0) {
        g_sum1[t] = 0; g_ss1[t] = 0;
        g_sum2[t] = 0; g_ss2[t] = 0;
        g_n3[t] = 0;
    }
    __syncthreads();

    // w2 pack from smem: tap t of channel b
    if (t < 9) {
        u64 wd = 0;
        #pragma unroll 8
        for (int ci = 0; ci < 64; ci++)
            wd |= (u64)(w2s[ci * 9 + t] > 0.f) << ci;
        g_w2b[b * 9 + t] = wd;
        w2bits[t] = wd;
    }
    __syncthreads();

    // border-correction table: 9 patterns for channel b
    if (t < 9) {
        const int rowc = t / 3, colc = t - rowc * 3;
        int corr = 0;
        #pragma unroll
        for (int tap = 0; tap < 9; tap++) {
            const int r = tap / 3, c = tap - r * 3;
            bool inval = (rowc == 1 && r == 0) || (rowc == 2 && r == 2) ||
                         (colc == 1 && c == 0) || (colc == 2 && c == 2);
            if (inval) corr += 64 - 2 * __popcll(w2bits[tap]);
        }
        g_ctab[t * 64 + b] = corr;
    }
}

// ---------------- K1: pack x (2 px/thread, float2), conv1, stats ----------------
__global__ __launch_bounds__(256) void k1_conv1(const float* __restrict__ x) {
    __shared__ u64 w1s[256];
    __shared__ int ssum[64], sss[64];
    const int tid = threadIdx.x;
    if (tid < 64) { ssum[tid] = 0; sss[tid] = 0; }
    w1s[tid] = g_w1b[tid];
    __syncthreads();

    const int q  = blockIdx.x * 256 + tid;   // 392*256 = NPAIR
    const int n  = q / 1568;
    const int hw = (q - n * 1568) * 2;
    const float* xp = x + (size_t)n * CIN * HW + hw;

    u64 v[2][4];   // [pixel][word]
    #pragma unroll
    for (int wi = 0; wi < 4; wi++) {
        u64 b0 = 0, b1 = 0;
        #pragma unroll 16
        for (int c = 0; c < 64; c++) {
            float2 xv = *reinterpret_cast<const float2*>(xp + (size_t)(wi * 64 + c) * HW);
            b0 |= (u64)(xv.x > 0.f) << c;
            b1 |= (u64)(xv.y > 0.f) << c;
        }
        v[0][wi] = b0; v[1][wi] = b1;
    }

    const int lane = tid & 31;

    #pragma unroll 1
    for (int g = 0; g < 8; g++) {
        int pk[2][4];   // [pixel][jj]
        #pragma unroll
        for (int jj = 0; jj < 4; jj++) {
            int sv[2][2];
            #pragma unroll
            for (int k = 0; k < 2; k++) {
                const int co = g * 8 + jj * 2 + k;
                const u64* wq = &w1s[co * 4];
                const u64 q0 = wq[0], q1 = wq[1], q2 = wq[2], q3 = wq[3];
                int stot = 0, qtot = 0;
                #pragma unroll
                for (int j = 0; j < 2; j++) {
                    int d = __popcll(v[j][0] ^ q0) + __popcll(v[j][1] ^ q1)
                          + __popcll(v[j][2] ^ q2) + __popcll(v[j][3] ^ q3);
                    int s = 256 - 2 * d;
                    sv[j][k] = s; stot += s; qtot += s * s;
                }
                int rs = __reduce_add_sync(0xFFFFFFFFu, stot);
                int rq = __reduce_add_sync(0xFFFFFFFFu, qtot);
                if (lane == 0) { atomicAdd(&ssum[co], rs); atomicAdd(&sss[co], rq); }
            }
            #pragma unroll
            for (int j = 0; j < 2; j++)
                pk[j][jj] = (sv[j][0] & 0xFFFF) | (sv[j][1] << 16);
        }
        #pragma unroll
        for (int j = 0; j < 2; j++)
            g_s1v[(size_t)g * NPIX + 2 * q + j] = make_int4(pk[j][0], pk[j][1], pk[j][2], pk[j][3]);
    }
    __syncthreads();
    if (tid < 64) {
        atomicAdd((u64*)&g_sum1[tid], (u64)(long long)ssum[tid]);
        atomicAdd((u64*)&g_ss1[tid],  (u64)(long long)sss[tid]);
    }
}

// ---------------- K2: BN1 threshold -> padded conv2 input bits ----------------
__global__ __launch_bounds__(256) void k2_bnpack1(const float* __restrict__ g1,
                                                  const float* __restrict__ b1) {
    __shared__ float As[64], Bs[64];
    const int tid = threadIdx.x;
    if (tid < 64) {
        double m   = (double)g_sum1[tid] / CNTD;
        double var = (double)g_ss1[tid] / CNTD - m * m;
        double r   = rsqrt(var + EPSD);
        double A   = (double)g1[tid] * r;
        As[tid] = (float)A;
        Bs[tid] = (float)((double)b1[tid] - A * m);
    }
    __syncthreads();
    const int p = blockIdx.x * 256 + tid;
    u64 v = 0;
    #pragma unroll
    for (int g = 0; g < 8; g++) {
        int4 q = g_s1v[(size_t)g * NPIX + p];
        int arr[4] = {q.x, q.y, q.z, q.w};
        #pragma unroll
        for (int k = 0; k < 4; k++) {
            const int co = g * 8 + k * 2;
            float lo = (float)(short)arr[k];
            float hi = (float)(short)(arr[k] >> 16);
            v |= (u64)(fmaf(As[co],     lo, Bs[co])     > 0.f) << co;
            v |= (u64)(fmaf(As[co + 1], hi, Bs[co + 1]) > 0.f) << (co + 1);
        }
    }
    const int n  = p / HW;
    const int hw = p - n * HW;
    const int h  = hw / WW;
    const int w  = hw - h * WW;
    g_a1p[(size_t)n * PADHW + (size_t)(h + 1) * PADW + (w + 1)] = v;
}

// ---------------- K3: conv2 (3x3, pad 1) + stats; smem staging, direct LDS ----------------
// Block = (batch n, 4 output rows). Stage the 6 padded rows once, then 8 warps
// (4 rows x 2 channel-halves) read taps straight from smem (no register window
// -> low regs -> high occupancy).
__global__ __launch_bounds__(256) void k3_conv2() {
    __shared__ u64 tile[6 * 64];   // 6 padded rows, pitch 64 (58 used)
    __shared__ int bsum[64], bsq[64];
    const int tid  = threadIdx.x;
    const int wid  = tid >> 5;
    const int lane = tid & 31;
    if (tid < 64) { bsum[tid] = 0; bsq[tid] = 0; }

    const int blk = blockIdx.x;          // 896 = 64 n * 14 row-quads
    const int n   = blk / 14;
    const int h0  = (blk - n * 14) * 4;  // first output row of this quad

    // stage padded rows h0..h0+5
    const u64* src = g_a1p + (size_t)n * PADHW + (size_t)h0 * PADW;
    for (int i = tid; i < 384; i += 256) {
        const int r = i >> 6, c = i & 63;
        if (c < PADW) tile[r * 64 + c] = src[r * PADW + c];
    }
    __syncthreads();

    const int ro   = wid >> 1;           // 0..3: output row within quad
    const int h    = h0 + ro;
    const int half = wid & 1;
    const int ch   = half * 32 + lane;

    const u64 wv0 = g_w2b[ch * 9 + 0], wv1 = g_w2b[ch * 9 + 1], wv2 = g_w2b[ch * 9 + 2];
    const u64 wv3 = g_w2b[ch * 9 + 3], wv4 = g_w2b[ch * 9 + 4], wv5 = g_w2b[ch * 9 + 5];
    const u64 wv6 = g_w2b[ch * 9 + 6], wv7 = g_w2b[ch * 9 + 7], wv8 = g_w2b[ch * 9 + 8];

    const int rowc = (h == 0) ? 1 : ((h == HH - 1) ? 2 : 0);
    const int corr_m = g_ctab[(rowc * 3 + 0) * 64 + ch];
    const int corr_l = g_ctab[(rowc * 3 + 1) * 64 + ch];
    const int corr_r = g_ctab[(rowc * 3 + 2) * 64 + ch];

    const u64* t0 = &tile[ro * 64];
    const u64* t1 = t0 + 64;
    const u64* t2 = t1 + 64;

    short* orow = g_s2 + (size_t)(n * HW + h * WW) * 64 + ch;
    int accs = 0, accq = 0;

    #pragma unroll 1
    for (int c = 0; c < 14; c++) {
        const int base = c * 4;
        #pragma unroll
        for (int j = 0; j < 4; j++) {
            const int w = base + j;
            int d = __popcll(t0[w] ^ wv0) + __popcll(t0[w+1] ^ wv1) + __popcll(t0[w+2] ^ wv2)
                  + __popcll(t1[w] ^ wv3) + __popcll(t1[w+1] ^ wv4) + __popcll(t1[w+2] ^ wv5)
                  + __popcll(t2[w] ^ wv6) + __popcll(t2[w+1] ^ wv7) + __popcll(t2[w+2] ^ wv8);
            const int corr = (w == 0) ? corr_l : ((w == WW - 1) ? corr_r : corr_m);
            int s = 576 - 2 * d - corr;
            accs += s; accq += s * s;
            orow[(size_t)w * 64] = (short)s;
        }
    }

    atomicAdd(&bsum[ch], accs);
    atomicAdd(&bsq[ch],  accq);
    __syncthreads();
    if (tid < 64) {
        atomicAdd((u64*)&g_sum2[tid], (u64)(long long)bsum[tid]);
        atomicAdd((u64*)&g_ss2[tid],  (u64)(long long)bsq[tid]);
    }
}

// ---------------- K4: BN2 threshold -> conv3 bits + ballot transpose ----------------
__global__ __launch_bounds__(256) void k4_pack2(const float* __restrict__ g2,
                                                const float* __restrict__ b2) {
    __shared__ float As[64], Bs[64];
    const int tid = threadIdx.x;
    if (tid < 64) {
        double m   = (double)g_sum2[tid] / CNTD;
        double var = (double)g_ss2[tid] / CNTD - m * m;
        double r   = rsqrt(var + EPSD);
        double A   = (double)g2[tid] * r;
        As[tid] = (float)A;
        Bs[tid] = (float)((double)b2[tid] - A * m);
    }
    __syncthreads();

    const int p = blockIdx.x * 256 + tid;   // 784 blocks
    const int4* sp = reinterpret_cast<const int4*>(g_s2 + (size_t)p * 64);
    u64 v = 0;
    #pragma unroll
    for (int g = 0; g < 8; g++) {
        int4 qq = sp[g];
        int arr[4] = {qq.x, qq.y, qq.z, qq.w};
        #pragma unroll
        for (int k = 0; k < 4; k++) {
            const int co = g * 8 + k * 2;
            float lo = (float)(short)arr[k];
            float hi = (float)(short)(arr[k] >> 16);
            v |= (u64)(fmaf(As[co],     lo, Bs[co])     > 0.f) << co;
            v |= (u64)(fmaf(As[co + 1], hi, Bs[co + 1]) > 0.f) << (co + 1);
        }
    }
    reinterpret_cast<u64*>(g_a2)[p] = v;

    // ballot transpose: warp's 32 pixels x 64 bits -> 64 u32 column words
    const int lane = tid & 31;
    const int gw   = p >> 5;
    u32 r0 = 0, r1 = 0;
    #pragma unroll
    for (int b = 0; b < 64; b++) {
        u32 bl = __ballot_sync(0xFFFFFFFFu, (u32)((v >> b) & 1ull));
        if (b == lane)      r0 = bl;
        if (b == lane + 32) r1 = bl;
    }
    g_t3[(size_t)gw * 64 + lane]      = r0;
    g_t3[(size_t)gw * 64 + 32 + lane] = r1;
}

// ---------------- K4g: gram matrix of conv3 input bit-columns ----------------
__global__ __launch_bounds__(256) void k4g_gram() {
    __shared__ u32 cw[64][65];   // [word][col]
    const int tid  = threadIdx.x;
    const int base = blockIdx.x * 64;   // 98 blocks * 64 words = NWRD
    for (int e = tid; e < 4096; e += 256) {
        const int w = e >> 6, col = e & 63;
        cw[w][col] = g_t3[(size_t)(base + w) * 64 + col];
    }
    __syncthreads();
    if (tid < 64) {
        int cnt = 0;
        #pragma unroll 8
        for (int w = 0; w < 64; w++) cnt += __popc(cw[w][tid]);
        atomicAdd(&g_n3[tid], cnt);
    }
    for (int e = tid; e < 4096; e += 256) {
        const int i = e >> 6, j = e & 63;
        if (i < j) {
            int d = 0;
            #pragma unroll 8
            for (int w = 0; w < 64; w++) d += __popc(cw[w][i] ^ cw[w][j]);
            atomicAdd(&g_G[e], d);
        }
    }
}

// ---------------- K5: conv3 stats from gram -> BN3 affine ----------------
__global__ void k5_fin3(const float* __restrict__ g3, const float* __restrict__ b3) {
    const int c = blockIdx.x;     // 256 blocks x 64 threads
    const int i = threadIdx.x;
    const u64 w = g_w3b[c];
    const int wi = ((int)((w >> i) & 1ull)) * 2 - 1;

    int inner = 0;
    #pragma unroll 8
    for (int j = 0; j < 64; j++) {
        const int wj = ((int)((w >> j) & 1ull)) * 2 - 1;
        int gij;
        if (i == j) gij = NPIX;
        else        gij = NPIX - 2 * g_G[(i < j) ? (i * 64 + j) : (j * 64 + i)];
        inner += wj * gij;
    }
    int c_sq = wi * inner;
    int c_s  = wi * (2 * g_n3[i] - NPIX);

    __shared__ int s_sq[2], s_s[2];
    int rsq = __reduce_add_sync(0xFFFFFFFFu, c_sq);
    int rs  = __reduce_add_sync(0xFFFFFFFFu, c_s);
    if ((i & 31) == 0) { s_sq[i >> 5] = rsq; s_s[i >> 5] = rs; }
    __syncthreads();
    if (i == 0) {
        long long ssq = (long long)s_sq[0] + s_sq[1];
        long long ss  = (long long)s_s[0]  + s_s[1];
        double m   = (double)ss / CNTD;
        double var = (double)ssq / CNTD - m * m;
        double r   = rsqrt(var + EPSD);
        double A   = (double)g3[c] * r;
        g_A3[c] = (float)A;
        g_B3[c] = (float)((double)b3[c] - A * m);
    }
}

// ---------------- K6: conv3 recompute + BN3 + residual + hardtanh ----------------
__global__ __launch_bounds__(256) void k6_final(const float* __restrict__ x,
                                                float* __restrict__ out) {
    __shared__ u64 w3s[8];
    __shared__ float As[8], Bs[8];
    const int tid = threadIdx.x;
    const int cg  = blockIdx.y;          // 32 channel groups of 8
    if (tid < 8) {
        w3s[tid] = g_w3b[cg * 8 + tid];
        As[tid]  = g_A3[cg * 8 + tid];
        Bs[tid]  = g_B3[cg * 8 + tid];
    }
    __syncthreads();

    const int q  = blockIdx.x * 256 + tid;   // NQUAD
    const int n  = q / 784;
    const int hw = (q - n * 784) * 4;
    ulonglong4 a = g_a2[q];
    u64 av0 = a.x, av1 = a.y, av2 = a.z, av3 = a.w;

    const size_t base = ((size_t)n * CIN + (size_t)cg * 8) * HW + hw;
    #pragma unroll
    for (int k = 0; k < 8; k++) {
        const u64 wv = w3s[k];
        const float A = As[k], B = Bs[k];
        float4 xv = *reinterpret_cast<const float4*>(x + base + (size_t)k * HW);
        float4 o;
        o.x = fminf(fmaxf(fmaf(A, (float)(64 - 2 * __popcll(av0 ^ wv)), B) + xv.x, -1.f), 1.f);
        o.y = fminf(fmaxf(fmaf(A, (float)(64 - 2 * __popcll(av1 ^ wv)), B) + xv.y, -1.f), 1.f);
        o.z = fminf(fmaxf(fmaf(A, (float)(64 - 2 * __popcll(av2 ^ wv)), B) + xv.z, -1.f), 1.f);
        o.w = fminf(fmaxf(fmaf(A, (float)(64 - 2 * __popcll(av3 ^ wv)), B) + xv.w, -1.f), 1.f);
        *reinterpret_cast<float4*>(out + base + (size_t)k * HW) = o;
    }
}

extern "C" void kernel_launch(void* const* d_in, const int* in_sizes, int n_in,
                              void* d_out, int out_size) {
    const float* x  = (const float*)d_in[0];
    const float* w1 = (const float*)d_in[1];
    const float* w2 = (const float*)d_in[2];
    const float* w3 = (const float*)d_in[3];
    const float* g1 = (const float*)d_in[4];
    const float* b1 = (const float*)d_in[5];
    const float* g2 = (const float*)d_in[6];
    const float* b2 = (const float*)d_in[7];
    const float* g3 = (const float*)d_in[8];
    const float* b3 = (const float*)d_in[9];
    float* out = (float*)d_out;

    k0_init<<<64, 64>>>(w1, w2, w3);
    k1_conv1<<<392, 256>>>(x);
    k2_bnpack1<<<784, 256>>>(g1, b1);
    k3_conv2<<<896, 256>>>();
    k4_pack2<<<784, 256>>>(g2, b2);
    k4g_gram<<<98, 256>>>();
    k5_fin3<<<256, 64>>>(g3, b3);
    dim3 g6(196, 32);
    k6_final<<<g6, 256>>>(x, out);
}